// round 2
// baseline (speedup 1.0000x reference)
#include <cuda_runtime.h>
#include <cuda_bf16.h>
#include <math.h>
#include <limits.h>

#define Nn    20000
#define Ee    320000
#define ETOT  340000   // Ee + Nn self loops
#define DIN   128
#define HIDC  128
#define NH1   4
#define F1    512      // NH1*HIDC
#define DOUT  32

// ---------------- scratch (device globals; allocation-free) ----------------
__device__ __align__(16) float g_h0  [Nn*DIN];
__device__ __align__(16) float g_xh1 [(size_t)Nn*F1];
__device__ __align__(16) float g_al1s[Nn*NH1];
__device__ __align__(16) float g_al1d[Nn*NH1];
__device__             int    g_m1  [Nn*NH1];
__device__             float  g_den1[Nn*NH1];
__device__ __align__(16) float g_e1  [(size_t)ETOT*NH1];
__device__ __align__(16) float g_agg1[(size_t)Nn*F1];
__device__ __align__(16) float g_h1  [(size_t)Nn*F1];
__device__ __align__(16) float g_xh2 [Nn*HIDC];
__device__             float  g_al2s[Nn];
__device__             float  g_al2d[Nn];
__device__             int    g_m2  [Nn];
__device__             float  g_den2[Nn];
__device__             float  g_e2  [ETOT];
__device__ __align__(16) float g_agg2[Nn*HIDC];
__device__ __align__(16) float g_h2  [Nn*HIDC];
__device__             int    g_src [ETOT];
__device__             int    g_dst [ETOT];
__device__             int    g_is32;

// ---------------- helpers ----------------
__device__ __forceinline__ float wsum(float v){
    #pragma unroll
    for (int o = 16; o; o >>= 1) v += __shfl_xor_sync(0xffffffffu, v, o);
    return v;
}
__device__ __forceinline__ float wmax(float v){
    #pragma unroll
    for (int o = 16; o; o >>= 1) v = fmaxf(v, __shfl_xor_sync(0xffffffffu, v, o));
    return v;
}
// order-preserving float<->int encoding for atomicMax
__device__ __forceinline__ int f2key(float f){ int i = __float_as_int(f); return i < 0 ? (i ^ 0x7fffffff) : i; }
__device__ __forceinline__ float key2f(int k){ return __int_as_float(k < 0 ? (k ^ 0x7fffffff) : k); }

__device__ __forceinline__ void red_add_v4(float* addr, float a, float b, float c, float d){
    asm volatile("red.global.add.v4.f32 [%0], {%1,%2,%3,%4};"
                 :: "l"(addr), "f"(a), "f"(b), "f"(c), "f"(d) : "memory");
}

__device__ __forceinline__ float gelu_exact(float x){
    return 0.5f * x * (1.0f + erff(x * 0.70710678118654752f));
}

// ---------------- edge dtype detection + decode ----------------
// If the buffer really holds int64 indices, every int64-interpreted value is in
// [0, Nn). If it holds int32 indices, an int64 read packs two random int32s ->
// astronomically out of range. Sample 4096 values to decide.
__global__ void detect_dtype(const long long* __restrict__ p){
    long long stride = (2LL * Ee) / 4096;
    if (stride < 1) stride = 1;
    long long idx = (long long)(blockIdx.x * blockDim.x + threadIdx.x) * stride;
    if (idx >= 2LL * Ee) return;
    long long v = p[idx];
    if (v < 0 || v >= Nn) atomicExch(&g_is32, 1);
}

__global__ void decode_edges(const int* __restrict__ p32){
    int e = blockIdx.x * blockDim.x + threadIdx.x;
    if (e >= ETOT) return;
    if (e < Ee){
        if (g_is32){ g_src[e] = p32[e];          g_dst[e] = p32[Ee + e]; }
        else       { g_src[e] = p32[2*e];        g_dst[e] = p32[2*Ee + 2*e]; }  // little-endian lo word
    } else {
        g_src[e] = g_dst[e] = e - Ee;
    }
}

// ---------------- LayerNorm (+optional bias in, +optional gelu out) ----------------
template<int D, bool GELU, bool BIAS>
__global__ void ln_kernel(const float* __restrict__ in, const float* __restrict__ bias,
                          const float* __restrict__ g, const float* __restrict__ b,
                          float* __restrict__ out){
    int row = blockIdx.x * (blockDim.x >> 5) + (threadIdx.x >> 5);
    if (row >= Nn) return;
    int lane = threadIdx.x & 31;
    constexpr int V = D / 128;           // float4s per lane
    float4 v[V];
    const float4* ir = (const float4*)(in + (size_t)row * D);
    float s = 0.f;
    #pragma unroll
    for (int i = 0; i < V; i++){
        v[i] = ir[lane + i*32];
        if (BIAS){
            float4 bb = ((const float4*)bias)[lane + i*32];
            v[i].x += bb.x; v[i].y += bb.y; v[i].z += bb.z; v[i].w += bb.w;
        }
        s += v[i].x + v[i].y + v[i].z + v[i].w;
    }
    s = wsum(s);
    float mu = s * (1.0f / D);
    float q = 0.f;
    #pragma unroll
    for (int i = 0; i < V; i++){
        float dx;
        dx = v[i].x - mu; q += dx*dx;
        dx = v[i].y - mu; q += dx*dx;
        dx = v[i].z - mu; q += dx*dx;
        dx = v[i].w - mu; q += dx*dx;
    }
    q = wsum(q);
    float rstd = rsqrtf(q * (1.0f / D) + 1e-5f);
    float4* orow = (float4*)(out + (size_t)row * D);
    #pragma unroll
    for (int i = 0; i < V; i++){
        float4 gg = ((const float4*)g)[lane + i*32];
        float4 bb2 = ((const float4*)b)[lane + i*32];
        float4 y;
        y.x = (v[i].x - mu) * rstd * gg.x + bb2.x;
        y.y = (v[i].y - mu) * rstd * gg.y + bb2.y;
        y.z = (v[i].z - mu) * rstd * gg.z + bb2.z;
        y.w = (v[i].w - mu) * rstd * gg.w + bb2.w;
        if (GELU){
            y.x = gelu_exact(y.x); y.y = gelu_exact(y.y);
            y.z = gelu_exact(y.z); y.w = gelu_exact(y.w);
        }
        orow[lane + i*32] = y;
    }
}

// ---------------- fp32 tiled GEMM: C[n,m] = A[n,k] @ B[k,m] ----------------
#define BM 64
#define BN 64
#define BK 16
__global__ void gemm_kernel(const float* __restrict__ A, const float* __restrict__ B,
                            float* __restrict__ C, int n, int k, int m){
    __shared__ float As[BK][BM + 4];
    __shared__ float Bs[BK][BN + 4];
    int tid = threadIdx.x;
    int block_m = blockIdx.y * BM;
    int block_n = blockIdx.x * BN;

    int a_row  = tid >> 2;          // 0..63
    int a_col4 = (tid & 3) * 4;     // 0,4,8,12
    int b_row  = tid >> 4;          // 0..15
    int b_col4 = (tid & 15) * 4;    // 0..60
    int ty = tid >> 4;              // 0..15 (m)
    int tx = tid & 15;              // 0..15 (n)

    float acc[4][4];
    #pragma unroll
    for (int i=0;i<4;i++)
        #pragma unroll
        for (int j=0;j<4;j++) acc[i][j] = 0.f;

    for (int k0 = 0; k0 < k; k0 += BK){
        float4 av = make_float4(0,0,0,0);
        int gr = block_m + a_row;
        if (gr < n) av = *(const float4*)&A[(size_t)gr * k + k0 + a_col4];
        As[a_col4+0][a_row] = av.x;
        As[a_col4+1][a_row] = av.y;
        As[a_col4+2][a_row] = av.z;
        As[a_col4+3][a_row] = av.w;

        float4 bv = *(const float4*)&B[(size_t)(k0 + b_row) * m + block_n + b_col4];
        *(float4*)&Bs[b_row][b_col4] = bv;
        __syncthreads();

        #pragma unroll
        for (int kk = 0; kk < BK; kk++){
            float4 a4 = *(float4*)&As[kk][ty*4];
            float4 b4 = *(float4*)&Bs[kk][tx*4];
            acc[0][0] += a4.x*b4.x; acc[0][1] += a4.x*b4.y; acc[0][2] += a4.x*b4.z; acc[0][3] += a4.x*b4.w;
            acc[1][0] += a4.y*b4.x; acc[1][1] += a4.y*b4.y; acc[1][2] += a4.y*b4.z; acc[1][3] += a4.y*b4.w;
            acc[2][0] += a4.z*b4.x; acc[2][1] += a4.z*b4.y; acc[2][2] += a4.z*b4.z; acc[2][3] += a4.z*b4.w;
            acc[3][0] += a4.w*b4.x; acc[3][1] += a4.w*b4.y; acc[3][2] += a4.w*b4.z; acc[3][3] += a4.w*b4.w;
        }
        __syncthreads();
    }
    #pragma unroll
    for (int i = 0; i < 4; i++){
        int r = block_m + ty*4 + i;
        if (r < n){
            float4 o = make_float4(acc[i][0], acc[i][1], acc[i][2], acc[i][3]);
            *(float4*)&C[(size_t)r * m + block_n + tx*4] = o;
        }
    }
}

// ---------------- attention logits per node ----------------
template<int H>
__global__ void attn_logits(const float* __restrict__ xh, const float* __restrict__ as_,
                            const float* __restrict__ ad_, float* __restrict__ als,
                            float* __restrict__ ald){
    int w = (blockIdx.x * blockDim.x + threadIdx.x) >> 5;
    if (w >= Nn * H) return;
    int lane = threadIdx.x & 31;
    int h = w % H;
    const float4* xr = (const float4*)(xh + (size_t)w * HIDC);
    float4 x  = xr[lane];
    float4 sv = ((const float4*)(as_ + h * HIDC))[lane];
    float4 dv = ((const float4*)(ad_ + h * HIDC))[lane];
    float s = x.x*sv.x + x.y*sv.y + x.z*sv.z + x.w*sv.w;
    float d = x.x*dv.x + x.y*dv.y + x.z*dv.z + x.w*dv.w;
    s = wsum(s); d = wsum(d);
    if (lane == 0){ als[w] = s; ald[w] = d; }
}

// ---------------- fill m arrays with INT_MIN ----------------
__global__ void fill_minima(int* __restrict__ m1, int* __restrict__ m2){
    int i = blockIdx.x * blockDim.x + threadIdx.x;
    if (i < Nn * NH1) m1[i] = INT_MIN;
    if (i < Nn)       m2[i] = INT_MIN;
}

// ---------------- edge pass A: logits + segment max ----------------
template<int H>
__global__ void edge_logits(const float* __restrict__ als, const float* __restrict__ ald,
                            float* __restrict__ ebuf, int* __restrict__ m){
    int e = blockIdx.x * blockDim.x + threadIdx.x;
    if (e >= ETOT) return;
    int s = g_src[e], d = g_dst[e];
    #pragma unroll
    for (int h = 0; h < H; h++){
        float v = als[s*H + h] + ald[d*H + h];
        v = v > 0.f ? v : 0.2f * v;
        ebuf[(size_t)e*H + h] = v;
        atomicMax(&m[d*H + h], f2key(v));
    }
}

// ---------------- edge pass B: exp + segment sum (in-place ex) ----------------
template<int H>
__global__ void edge_exp(float* __restrict__ ebuf, const int* __restrict__ m,
                         float* __restrict__ den){
    int e = blockIdx.x * blockDim.x + threadIdx.x;
    if (e >= ETOT) return;
    int d = g_dst[e];
    #pragma unroll
    for (int h = 0; h < H; h++){
        float v = ebuf[(size_t)e*H + h];
        float mx = key2f(m[d*H + h]);
        float ex = expf(v - mx);
        ebuf[(size_t)e*H + h] = ex;
        atomicAdd(&den[d*H + h], ex);
    }
}

// ---------------- edge pass C: scatter alpha * xh[src] ----------------
template<int H>
__global__ void edge_scatter(const float* __restrict__ ebuf, const float* __restrict__ den,
                             const float* __restrict__ xh, float* __restrict__ agg){
    int w = (blockIdx.x * blockDim.x + threadIdx.x) >> 5;
    if (w >= ETOT * H) return;
    int lane = threadIdx.x & 31;
    int e = w / H;
    int h = w - e * H;
    int s = g_src[e], d = g_dst[e];
    float alpha = ebuf[(size_t)e*H + h] / den[d*H + h];
    const float4* xr = (const float4*)(xh + (size_t)s * (H * HIDC) + h * HIDC);
    float4 v = xr[lane];
    float* ar = agg + (size_t)d * (H * HIDC) + h * HIDC + lane * 4;
    red_add_v4(ar, v.x * alpha, v.y * alpha, v.z * alpha, v.w * alpha);
}

// ---------------- fused output projection + log_softmax ----------------
__global__ void out_proj(const float* __restrict__ h2, const float* __restrict__ Wo,
                         const float* __restrict__ bo, float* __restrict__ out){
    int w = (blockIdx.x * blockDim.x + threadIdx.x) >> 5;
    if (w >= Nn) return;
    int lane = threadIdx.x & 31;
    const float* hr = h2 + (size_t)w * HIDC;
    float acc = bo[lane];
    #pragma unroll 8
    for (int k = 0; k < HIDC; k++)
        acc += hr[k] * Wo[k * DOUT + lane];
    float mx = wmax(acc);
    float ex = expf(acc - mx);
    float sm = wsum(ex);
    out[(size_t)w * DOUT + lane] = acc - mx - logf(sm);
}

// ---------------- launch ----------------
extern "C" void kernel_launch(void* const* d_in, const int* in_sizes, int n_in,
                              void* d_out, int out_size){
    const float*     x      = (const float*)d_in[0];
    const void*      ei     = d_in[1];
    const float*     g_in   = (const float*)d_in[2];
    const float*     b_in   = (const float*)d_in[3];
    const float*     W1     = (const float*)d_in[4];
    const float*     att1_s = (const float*)d_in[5];
    const float*     att1_d = (const float*)d_in[6];
    const float*     bias1  = (const float*)d_in[7];
    const float*     g1     = (const float*)d_in[8];
    const float*     b1     = (const float*)d_in[9];
    const float*     W2     = (const float*)d_in[10];
    const float*     att2_s = (const float*)d_in[11];
    const float*     att2_d = (const float*)d_in[12];
    const float*     bias2  = (const float*)d_in[13];
    const float*     g2     = (const float*)d_in[14];
    const float*     b2     = (const float*)d_in[15];
    const float*     Wo     = (const float*)d_in[16];
    const float*     bo     = (const float*)d_in[17];
    float* out = (float*)d_out;

    void *p_h0, *p_xh1, *p_al1s, *p_al1d, *p_m1, *p_den1, *p_e1, *p_agg1, *p_h1;
    void *p_xh2, *p_al2s, *p_al2d, *p_m2, *p_den2, *p_e2, *p_agg2, *p_h2, *p_is32;
    cudaGetSymbolAddress(&p_h0,   g_h0);
    cudaGetSymbolAddress(&p_xh1,  g_xh1);
    cudaGetSymbolAddress(&p_al1s, g_al1s);
    cudaGetSymbolAddress(&p_al1d, g_al1d);
    cudaGetSymbolAddress(&p_m1,   g_m1);
    cudaGetSymbolAddress(&p_den1, g_den1);
    cudaGetSymbolAddress(&p_e1,   g_e1);
    cudaGetSymbolAddress(&p_agg1, g_agg1);
    cudaGetSymbolAddress(&p_h1,   g_h1);
    cudaGetSymbolAddress(&p_xh2,  g_xh2);
    cudaGetSymbolAddress(&p_al2s, g_al2s);
    cudaGetSymbolAddress(&p_al2d, g_al2d);
    cudaGetSymbolAddress(&p_m2,   g_m2);
    cudaGetSymbolAddress(&p_den2, g_den2);
    cudaGetSymbolAddress(&p_e2,   g_e2);
    cudaGetSymbolAddress(&p_agg2, g_agg2);
    cudaGetSymbolAddress(&p_h2,   g_h2);
    cudaGetSymbolAddress(&p_is32, g_is32);

    const int T = 256;
    const int warpsPB = T / 32;

    // ---- edge dtype detection + decode ----
    cudaMemsetAsync(p_is32, 0, sizeof(int));
    detect_dtype<<<16, 256>>>((const long long*)ei);
    decode_edges<<<(ETOT + T - 1)/T, T>>>((const int*)ei);

    // init accumulators
    cudaMemsetAsync(p_agg1, 0, (size_t)Nn * F1 * sizeof(float));
    cudaMemsetAsync(p_agg2, 0, (size_t)Nn * HIDC * sizeof(float));
    cudaMemsetAsync(p_den1, 0, (size_t)Nn * NH1 * sizeof(float));
    cudaMemsetAsync(p_den2, 0, (size_t)Nn * sizeof(float));
    fill_minima<<<(Nn*NH1 + T - 1)/T, T>>>((int*)p_m1, (int*)p_m2);

    // ---- input LN ----
    ln_kernel<128, false, false><<<(Nn + warpsPB - 1)/warpsPB, T>>>(x, nullptr, g_in, b_in, (float*)p_h0);

    // ---- GAT layer 1 ----
    {
        dim3 grid(F1/BN, (Nn + BM - 1)/BM);
        gemm_kernel<<<grid, 256>>>((const float*)p_h0, W1, (float*)p_xh1, Nn, DIN, F1);
    }
    attn_logits<NH1><<<(Nn*NH1 + warpsPB - 1)/warpsPB, T>>>((const float*)p_xh1, att1_s, att1_d,
                                                            (float*)p_al1s, (float*)p_al1d);
    edge_logits<NH1><<<(ETOT + T - 1)/T, T>>>((const float*)p_al1s, (const float*)p_al1d,
                                              (float*)p_e1, (int*)p_m1);
    edge_exp<NH1><<<(ETOT + T - 1)/T, T>>>((float*)p_e1, (const int*)p_m1, (float*)p_den1);
    {
        long long warps = (long long)ETOT * NH1;
        int blocks = (int)((warps + warpsPB - 1) / warpsPB);
        edge_scatter<NH1><<<blocks, T>>>((const float*)p_e1, (const float*)p_den1,
                                         (const float*)p_xh1, (float*)p_agg1);
    }
    ln_kernel<512, true, true><<<(Nn + warpsPB - 1)/warpsPB, T>>>((const float*)p_agg1, bias1, g1, b1,
                                                                  (float*)p_h1);

    // ---- GAT layer 2 ----
    {
        dim3 grid(HIDC/BN, (Nn + BM - 1)/BM);
        gemm_kernel<<<grid, 256>>>((const float*)p_h1, W2, (float*)p_xh2, Nn, F1, HIDC);
    }
    attn_logits<1><<<(Nn + warpsPB - 1)/warpsPB, T>>>((const float*)p_xh2, att2_s, att2_d,
                                                      (float*)p_al2s, (float*)p_al2d);
    edge_logits<1><<<(ETOT + T - 1)/T, T>>>((const float*)p_al2s, (const float*)p_al2d,
                                            (float*)p_e2, (int*)p_m2);
    edge_exp<1><<<(ETOT + T - 1)/T, T>>>((float*)p_e2, (const int*)p_m2, (float*)p_den2);
    {
        int blocks = (ETOT + warpsPB - 1) / warpsPB;
        edge_scatter<1><<<blocks, T>>>((const float*)p_e2, (const float*)p_den2,
                                       (const float*)p_xh2, (float*)p_agg2);
    }
    ln_kernel<128, true, true><<<(Nn + warpsPB - 1)/warpsPB, T>>>((const float*)p_agg2, bias2, g2, b2,
                                                                  (float*)p_h2);

    // ---- output projection + log_softmax ----
    out_proj<<<(Nn + warpsPB - 1)/warpsPB, T>>>((const float*)p_h2, Wo, bo, out);
}

// round 6
// speedup vs baseline: 1.3384x; 1.3384x over previous
#include <cuda_runtime.h>
#include <cuda_bf16.h>
#include <math.h>
#include <limits.h>

#define Nn    20000
#define Ee    320000
#define ETOT  340000   // Ee + Nn self loops
#define DIN   128
#define HIDC  128
#define NH1   4
#define F1    512      // NH1*HIDC
#define DOUT  32

// ---------------- scratch (device globals; allocation-free) ----------------
__device__ __align__(16) float g_h0  [Nn*DIN];
__device__ __align__(16) float g_xh1 [(size_t)Nn*F1];
__device__ __align__(16) float g_al1s[Nn*NH1];
__device__ __align__(16) float g_al1d[Nn*NH1];
__device__             int    g_m1  [Nn*NH1];
__device__ __align__(16) float g_den1[Nn*NH1];
__device__ __align__(16) float g_e1  [(size_t)ETOT*NH1];
__device__ __align__(16) float g_agg1[(size_t)Nn*F1];
__device__ __align__(16) float g_h1  [(size_t)Nn*F1];
__device__ __align__(16) float g_xh2 [Nn*HIDC];
__device__             float  g_al2s[Nn];
__device__             float  g_al2d[Nn];
__device__             int    g_m2  [Nn];
__device__             float  g_den2[Nn];
__device__             float  g_e2  [ETOT];
__device__ __align__(16) float g_agg2[Nn*HIDC];
__device__ __align__(16) float g_h2  [Nn*HIDC];
__device__             int    g_src [ETOT];
__device__             int    g_dst [ETOT];
__device__             int    g_is32;

// ---------------- helpers ----------------
__device__ __forceinline__ float wsum(float v){
    #pragma unroll
    for (int o = 16; o; o >>= 1) v += __shfl_xor_sync(0xffffffffu, v, o);
    return v;
}
__device__ __forceinline__ float wmax(float v){
    #pragma unroll
    for (int o = 16; o; o >>= 1) v = fmaxf(v, __shfl_xor_sync(0xffffffffu, v, o));
    return v;
}
__device__ __forceinline__ int f2key(float f){ int i = __float_as_int(f); return i < 0 ? (i ^ 0x7fffffff) : i; }
__device__ __forceinline__ float key2f(int k){ return __int_as_float(k < 0 ? (k ^ 0x7fffffff) : k); }

__device__ __forceinline__ void red_add_v4(float* addr, float a, float b, float c, float d){
    asm volatile("red.global.add.v4.f32 [%0], {%1,%2,%3,%4};"
                 :: "l"(addr), "f"(a), "f"(b), "f"(c), "f"(d) : "memory");
}

__device__ __forceinline__ float gelu_exact(float x){
    return 0.5f * x * (1.0f + erff(x * 0.70710678118654752f));
}

__device__ __forceinline__ unsigned tf32_of(float x){
    unsigned u; asm("cvt.rna.tf32.f32 %0, %1;" : "=r"(u) : "f"(x)); return u;
}

// ---------------- edge dtype detection + decode ----------------
__global__ void detect_dtype(const long long* __restrict__ p){
    long long stride = (2LL * Ee) / 4096;
    if (stride < 1) stride = 1;
    long long idx = (long long)(blockIdx.x * blockDim.x + threadIdx.x) * stride;
    if (idx >= 2LL * Ee) return;
    long long v = p[idx];
    if (v < 0 || v >= Nn) atomicExch(&g_is32, 1);
}

__global__ void decode_edges(const int* __restrict__ p32){
    int e = blockIdx.x * blockDim.x + threadIdx.x;
    if (e >= ETOT) return;
    if (e < Ee){
        if (g_is32){ g_src[e] = p32[e];          g_dst[e] = p32[Ee + e]; }
        else       { g_src[e] = p32[2*e];        g_dst[e] = p32[2*Ee + 2*e]; }
    } else {
        g_src[e] = g_dst[e] = e - Ee;
    }
}

// ---------------- LayerNorm (+optional bias in, +optional gelu out) ----------------
template<int D, bool GELU, bool BIAS>
__global__ void ln_kernel(const float* __restrict__ in, const float* __restrict__ bias,
                          const float* __restrict__ g, const float* __restrict__ b,
                          float* __restrict__ out){
    int row = blockIdx.x * (blockDim.x >> 5) + (threadIdx.x >> 5);
    if (row >= Nn) return;
    int lane = threadIdx.x & 31;
    constexpr int V = D / 128;
    float4 v[V];
    const float4* ir = (const float4*)(in + (size_t)row * D);
    float s = 0.f;
    #pragma unroll
    for (int i = 0; i < V; i++){
        v[i] = ir[lane + i*32];
        if (BIAS){
            float4 bb = ((const float4*)bias)[lane + i*32];
            v[i].x += bb.x; v[i].y += bb.y; v[i].z += bb.z; v[i].w += bb.w;
        }
        s += v[i].x + v[i].y + v[i].z + v[i].w;
    }
    s = wsum(s);
    float mu = s * (1.0f / D);
    float q = 0.f;
    #pragma unroll
    for (int i = 0; i < V; i++){
        float dx;
        dx = v[i].x - mu; q += dx*dx;
        dx = v[i].y - mu; q += dx*dx;
        dx = v[i].z - mu; q += dx*dx;
        dx = v[i].w - mu; q += dx*dx;
    }
    q = wsum(q);
    float rstd = rsqrtf(q * (1.0f / D) + 1e-5f);
    float4* orow = (float4*)(out + (size_t)row * D);
    #pragma unroll
    for (int i = 0; i < V; i++){
        float4 gg = ((const float4*)g)[lane + i*32];
        float4 bb2 = ((const float4*)b)[lane + i*32];
        float4 y;
        y.x = (v[i].x - mu) * rstd * gg.x + bb2.x;
        y.y = (v[i].y - mu) * rstd * gg.y + bb2.y;
        y.z = (v[i].z - mu) * rstd * gg.z + bb2.z;
        y.w = (v[i].w - mu) * rstd * gg.w + bb2.w;
        if (GELU){
            y.x = gelu_exact(y.x); y.y = gelu_exact(y.y);
            y.z = gelu_exact(y.z); y.w = gelu_exact(y.w);
        }
        orow[lane + i*32] = y;
    }
}

// ---------------- tf32 tensor-core GEMM: C[n,m] = A[n,k] @ B[k,m] ----------------
// BM=128, BN=64, BK=32, 256 threads (8 warps, 4x2 of 32x32), mma.m16n8k8.tf32
#define GBM 128
#define GBN 64
#define GBK 32
#define AS_STRIDE (GBK + 4)
#define BS_STRIDE (GBN + 4)

__global__ void __launch_bounds__(256, 2) gemm_tf32(const float* __restrict__ A,
                                                    const float* __restrict__ B,
                                                    float* __restrict__ C,
                                                    int n, int k, int m){
    __shared__ float As[GBM][AS_STRIDE];
    __shared__ float Bs[GBK][BS_STRIDE];

    int tid  = threadIdx.x;
    int wid  = tid >> 5;
    int lane = tid & 31;
    int wm   = (wid & 3) * 32;     // warp m offset in tile
    int wn   = (wid >> 2) * 32;    // warp n offset in tile
    int grp  = lane >> 2;          // 0..7
    int tg   = lane & 3;           // 0..3

    int bm = blockIdx.y * GBM;
    int bn = blockIdx.x * GBN;

    float acc[2][4][4];
    #pragma unroll
    for (int i=0;i<2;i++)
        #pragma unroll
        for (int j=0;j<4;j++)
            #pragma unroll
            for (int l=0;l<4;l++) acc[i][j][l] = 0.f;

    int arow  = tid >> 3;          // 0..31
    int acol  = (tid & 7) * 4;     // 0..28
    int brow  = tid >> 4;          // 0..15
    int bcol  = (tid & 15) * 4;    // 0..60

    for (int k0 = 0; k0 < k; k0 += GBK){
        // load A tile (128 x 32)
        #pragma unroll
        for (int i = 0; i < 4; i++){
            int row = arow + i*32;
            float4 v = make_float4(0,0,0,0);
            int gr = bm + row;
            if (gr < n) v = *(const float4*)&A[(size_t)gr * k + k0 + acol];
            As[row][acol+0] = __uint_as_float(tf32_of(v.x));
            As[row][acol+1] = __uint_as_float(tf32_of(v.y));
            As[row][acol+2] = __uint_as_float(tf32_of(v.z));
            As[row][acol+3] = __uint_as_float(tf32_of(v.w));
        }
        // load B tile (32 x 64)
        #pragma unroll
        for (int i = 0; i < 2; i++){
            int row = brow + i*16;
            float4 v = *(const float4*)&B[(size_t)(k0 + row) * m + bn + bcol];
            Bs[row][bcol+0] = __uint_as_float(tf32_of(v.x));
            Bs[row][bcol+1] = __uint_as_float(tf32_of(v.y));
            Bs[row][bcol+2] = __uint_as_float(tf32_of(v.z));
            Bs[row][bcol+3] = __uint_as_float(tf32_of(v.w));
        }
        __syncthreads();

        #pragma unroll
        for (int kk = 0; kk < 4; kk++){
            unsigned a[2][4], bfr[4][2];
            #pragma unroll
            for (int mt = 0; mt < 2; mt++){
                int r = wm + mt*16 + grp;
                int c = kk*8 + tg;
                a[mt][0] = __float_as_uint(As[r    ][c    ]);
                a[mt][1] = __float_as_uint(As[r + 8][c    ]);
                a[mt][2] = __float_as_uint(As[r    ][c + 4]);
                a[mt][3] = __float_as_uint(As[r + 8][c + 4]);
            }
            #pragma unroll
            for (int nt = 0; nt < 4; nt++){
                int c = wn + nt*8 + grp;
                int r = kk*8 + tg;
                bfr[nt][0] = __float_as_uint(Bs[r    ][c]);
                bfr[nt][1] = __float_as_uint(Bs[r + 4][c]);
            }
            #pragma unroll
            for (int mt = 0; mt < 2; mt++)
                #pragma unroll
                for (int nt = 0; nt < 4; nt++){
                    asm volatile(
                        "mma.sync.aligned.m16n8k8.row.col.f32.tf32.tf32.f32 "
                        "{%0,%1,%2,%3}, {%4,%5,%6,%7}, {%8,%9}, {%0,%1,%2,%3};"
                        : "+f"(acc[mt][nt][0]), "+f"(acc[mt][nt][1]),
                          "+f"(acc[mt][nt][2]), "+f"(acc[mt][nt][3])
                        : "r"(a[mt][0]), "r"(a[mt][1]), "r"(a[mt][2]), "r"(a[mt][3]),
                          "r"(bfr[nt][0]), "r"(bfr[nt][1]));
                }
        }
        __syncthreads();
    }

    // store C
    #pragma unroll
    for (int mt = 0; mt < 2; mt++){
        int r0 = bm + wm + mt*16 + grp;
        int r1 = r0 + 8;
        #pragma unroll
        for (int nt = 0; nt < 4; nt++){
            int c = bn + wn + nt*8 + 2*tg;
            if (r0 < n) *(float2*)&C[(size_t)r0 * m + c] = make_float2(acc[mt][nt][0], acc[mt][nt][1]);
            if (r1 < n) *(float2*)&C[(size_t)r1 * m + c] = make_float2(acc[mt][nt][2], acc[mt][nt][3]);
        }
    }
}

// ---------------- attention logits per node ----------------
template<int H>
__global__ void attn_logits(const float* __restrict__ xh, const float* __restrict__ as_,
                            const float* __restrict__ ad_, float* __restrict__ als,
                            float* __restrict__ ald){
    int w = (blockIdx.x * blockDim.x + threadIdx.x) >> 5;
    if (w >= Nn * H) return;
    int lane = threadIdx.x & 31;
    int h = w % H;
    const float4* xr = (const float4*)(xh + (size_t)w * HIDC);
    float4 x  = xr[lane];
    float4 sv = ((const float4*)(as_ + h * HIDC))[lane];
    float4 dv = ((const float4*)(ad_ + h * HIDC))[lane];
    float s = x.x*sv.x + x.y*sv.y + x.z*sv.z + x.w*sv.w;
    float d = x.x*dv.x + x.y*dv.y + x.z*dv.z + x.w*dv.w;
    s = wsum(s); d = wsum(d);
    if (lane == 0){ als[w] = s; ald[w] = d; }
}

// ---------------- fill m arrays with INT_MIN ----------------
__global__ void fill_minima(int* __restrict__ m1, int* __restrict__ m2){
    int i = blockIdx.x * blockDim.x + threadIdx.x;
    if (i < Nn * NH1) m1[i] = INT_MIN;
    if (i < Nn)       m2[i] = INT_MIN;
}

// ---------------- edge pass A: logits + segment max ----------------
template<int H>
__global__ void edge_logits(const float* __restrict__ als, const float* __restrict__ ald,
                            float* __restrict__ ebuf, int* __restrict__ m){
    int e = blockIdx.x * blockDim.x + threadIdx.x;
    if (e >= ETOT) return;
    int s = g_src[e], d = g_dst[e];
    #pragma unroll
    for (int h = 0; h < H; h++){
        float v = als[s*H + h] + ald[d*H + h];
        v = v > 0.f ? v : 0.2f * v;
        ebuf[(size_t)e*H + h] = v;
        atomicMax(&m[d*H + h], f2key(v));
    }
}

// ---------------- edge pass B: exp + segment sum (in-place ex) ----------------
template<int H>
__global__ void edge_exp(float* __restrict__ ebuf, const int* __restrict__ m,
                         float* __restrict__ den){
    int e = blockIdx.x * blockDim.x + threadIdx.x;
    if (e >= ETOT) return;
    int d = g_dst[e];
    #pragma unroll
    for (int h = 0; h < H; h++){
        float v = ebuf[(size_t)e*H + h];
        float mx = key2f(m[d*H + h]);
        float ex = expf(v - mx);
        ebuf[(size_t)e*H + h] = ex;
        atomicAdd(&den[d*H + h], ex);
    }
}

// ---------------- edge pass C (H=4): one warp per edge, all 512 ch ----------------
__global__ void edge_scatter4(const float4* __restrict__ ebuf4, const float4* __restrict__ den4,
                              const float* __restrict__ xh, float* __restrict__ agg){
    int w = (blockIdx.x * blockDim.x + threadIdx.x) >> 5;
    if (w >= ETOT) return;
    int lane = threadIdx.x & 31;
    int s = g_src[w], d = g_dst[w];
    float4 ex = ebuf4[w];
    float4 dn = den4[d];
    float al[4] = { ex.x/dn.x, ex.y/dn.y, ex.z/dn.z, ex.w/dn.w };
    const float4* xr = (const float4*)(xh + (size_t)s * F1);
    float* ar = agg + (size_t)d * F1;
    #pragma unroll
    for (int h = 0; h < 4; h++){
        float4 v = xr[h*32 + lane];
        float a = al[h];
        red_add_v4(ar + h*128 + lane*4, v.x*a, v.y*a, v.z*a, v.w*a);
    }
}

// ---------------- edge pass C (H=1) ----------------
__global__ void edge_scatter1(const float* __restrict__ ebuf, const float* __restrict__ den,
                              const float* __restrict__ xh, float* __restrict__ agg){
    int w = (blockIdx.x * blockDim.x + threadIdx.x) >> 5;
    if (w >= ETOT) return;
    int lane = threadIdx.x & 31;
    int s = g_src[w], d = g_dst[w];
    float alpha = ebuf[w] / den[d];
    const float4* xr = (const float4*)(xh + (size_t)s * HIDC);
    float4 v = xr[lane];
    float* ar = agg + (size_t)d * HIDC + lane * 4;
    red_add_v4(ar, v.x*alpha, v.y*alpha, v.z*alpha, v.w*alpha);
}

// ---------------- fused output projection + log_softmax ----------------
__global__ void out_proj(const float* __restrict__ h2, const float* __restrict__ Wo,
                         const float* __restrict__ bo, float* __restrict__ out){
    int w = (blockIdx.x * blockDim.x + threadIdx.x) >> 5;
    if (w >= Nn) return;
    int lane = threadIdx.x & 31;
    const float* hr = h2 + (size_t)w * HIDC;
    float acc = bo[lane];
    #pragma unroll 8
    for (int k = 0; k < HIDC; k++)
        acc += hr[k] * Wo[k * DOUT + lane];
    float mx = wmax(acc);
    float ex = expf(acc - mx);
    float sm = wsum(ex);
    out[(size_t)w * DOUT + lane] = acc - mx - logf(sm);
}

// ---------------- launch ----------------
extern "C" void kernel_launch(void* const* d_in, const int* in_sizes, int n_in,
                              void* d_out, int out_size){
    const float*     x      = (const float*)d_in[0];
    const void*      ei     = d_in[1];
    const float*     g_in   = (const float*)d_in[2];
    const float*     b_in   = (const float*)d_in[3];
    const float*     W1     = (const float*)d_in[4];
    const float*     att1_s = (const float*)d_in[5];
    const float*     att1_d = (const float*)d_in[6];
    const float*     bias1  = (const float*)d_in[7];
    const float*     g1     = (const float*)d_in[8];
    const float*     b1     = (const float*)d_in[9];
    const float*     W2     = (const float*)d_in[10];
    const float*     att2_s = (const float*)d_in[11];
    const float*     att2_d = (const float*)d_in[12];
    const float*     bias2  = (const float*)d_in[13];
    const float*     g2     = (const float*)d_in[14];
    const float*     b2     = (const float*)d_in[15];
    const float*     Wo     = (const float*)d_in[16];
    const float*     bo     = (const float*)d_in[17];
    float* out = (float*)d_out;

    void *p_h0, *p_xh1, *p_al1s, *p_al1d, *p_m1, *p_den1, *p_e1, *p_agg1, *p_h1;
    void *p_xh2, *p_al2s, *p_al2d, *p_m2, *p_den2, *p_e2, *p_agg2, *p_h2, *p_is32;
    cudaGetSymbolAddress(&p_h0,   g_h0);
    cudaGetSymbolAddress(&p_xh1,  g_xh1);
    cudaGetSymbolAddress(&p_al1s, g_al1s);
    cudaGetSymbolAddress(&p_al1d, g_al1d);
    cudaGetSymbolAddress(&p_m1,   g_m1);
    cudaGetSymbolAddress(&p_den1, g_den1);
    cudaGetSymbolAddress(&p_e1,   g_e1);
    cudaGetSymbolAddress(&p_agg1, g_agg1);
    cudaGetSymbolAddress(&p_h1,   g_h1);
    cudaGetSymbolAddress(&p_xh2,  g_xh2);
    cudaGetSymbolAddress(&p_al2s, g_al2s);
    cudaGetSymbolAddress(&p_al2d, g_al2d);
    cudaGetSymbolAddress(&p_m2,   g_m2);
    cudaGetSymbolAddress(&p_den2, g_den2);
    cudaGetSymbolAddress(&p_e2,   g_e2);
    cudaGetSymbolAddress(&p_agg2, g_agg2);
    cudaGetSymbolAddress(&p_h2,   g_h2);
    cudaGetSymbolAddress(&p_is32, g_is32);

    const int T = 256;
    const int warpsPB = T / 32;

    // ---- edge dtype detection + decode ----
    cudaMemsetAsync(p_is32, 0, sizeof(int));
    detect_dtype<<<16, 256>>>((const long long*)ei);
    decode_edges<<<(ETOT + T - 1)/T, T>>>((const int*)ei);

    // init accumulators
    cudaMemsetAsync(p_agg1, 0, (size_t)Nn * F1 * sizeof(float));
    cudaMemsetAsync(p_agg2, 0, (size_t)Nn * HIDC * sizeof(float));
    cudaMemsetAsync(p_den1, 0, (size_t)Nn * NH1 * sizeof(float));
    cudaMemsetAsync(p_den2, 0, (size_t)Nn * sizeof(float));
    fill_minima<<<(Nn*NH1 + T - 1)/T, T>>>((int*)p_m1, (int*)p_m2);

    // ---- input LN ----
    ln_kernel<128, false, false><<<(Nn + warpsPB - 1)/warpsPB, T>>>(x, nullptr, g_in, b_in, (float*)p_h0);

    // ---- GAT layer 1 ----
    {
        dim3 grid(F1/GBN, (Nn + GBM - 1)/GBM);
        gemm_tf32<<<grid, 256>>>((const float*)p_h0, W1, (float*)p_xh1, Nn, DIN, F1);
    }
    attn_logits<NH1><<<(Nn*NH1 + warpsPB - 1)/warpsPB, T>>>((const float*)p_xh1, att1_s, att1_d,
                                                            (float*)p_al1s, (float*)p_al1d);
    edge_logits<NH1><<<(ETOT + T - 1)/T, T>>>((const float*)p_al1s, (const float*)p_al1d,
                                              (float*)p_e1, (int*)p_m1);
    edge_exp<NH1><<<(ETOT + T - 1)/T, T>>>((float*)p_e1, (const int*)p_m1, (float*)p_den1);
    edge_scatter4<<<(ETOT + warpsPB - 1)/warpsPB, T>>>((const float4*)p_e1, (const float4*)p_den1,
                                                       (const float*)p_xh1, (float*)p_agg1);
    ln_kernel<512, true, true><<<(Nn + warpsPB - 1)/warpsPB, T>>>((const float*)p_agg1, bias1, g1, b1,
                                                                  (float*)p_h1);

    // ---- GAT layer 2 ----
    {
        dim3 grid(HIDC/GBN, (Nn + GBM - 1)/GBM);
        gemm_tf32<<<grid, 256>>>((const float*)p_h1, W2, (float*)p_xh2, Nn, F1, HIDC);
    }
    attn_logits<1><<<(Nn + warpsPB - 1)/warpsPB, T>>>((const float*)p_xh2, att2_s, att2_d,
                                                      (float*)p_al2s, (float*)p_al2d);
    edge_logits<1><<<(ETOT + T - 1)/T, T>>>((const float*)p_al2s, (const float*)p_al2d,
                                            (float*)p_e2, (int*)p_m2);
    edge_exp<1><<<(ETOT + T - 1)/T, T>>>((float*)p_e2, (const int*)p_m2, (float*)p_den2);
    edge_scatter1<<<(ETOT + warpsPB - 1)/warpsPB, T>>>((const float*)p_e2, (const float*)p_den2,
                                                       (const float*)p_xh2, (float*)p_agg2);
    ln_kernel<128, true, true><<<(Nn + warpsPB - 1)/warpsPB, T>>>((const float*)p_agg2, bias2, g2, b2,
                                                                  (float*)p_h2);

    // ---- output projection + log_softmax ----
    out_proj<<<(Nn + warpsPB - 1)/warpsPB, T>>>((const float*)p_h2, Wo, bo, out);
}